// round 1
// baseline (speedup 1.0000x reference)
#include <cuda_runtime.h>

#define FULLMASK 0xffffffffu

namespace {

constexpr int kB = 2;
constexpr int kInCh = 2;
constexpr int kOutCh = 4;
constexpr int kH = 128;
constexpr int kW = 128;
constexpr int kHH = 64;
constexpr int kWW = 64;
constexpr int kNL = 4;
constexpr int kNPatch = kB * kHH * kWW;       // 8192 patches, one warp each
constexpr int kThreads = 256;
constexpr int kWarpsPerBlock = kThreads / 32; // 8
constexpr int kBlocks = kNPatch / kWarpsPerBlock; // 1024

// State layout: 8-qubit state (256 complex amps) per warp.
// Flat index bit 7..0 (C-order; qubit q <-> bit (7-q)).
// Lane id = bits [7:3] of index, register slot r = bits [2:0].
// => qubits 0..4 are "lane qubits" (lane-bit masks 16,8,4,2,1),
//    qubits 5..7 are "register qubits" (reg-bit masks 4,2,1).

template <int Q>
__device__ __forceinline__ void rx_gate(float (&re)[8], float (&im)[8], float c, float s) {
    // RX(theta): new0 = c*a0 - i*s*a1 ; new1 = c*a1 - i*s*a0  (symmetric in 0<->1)
    if constexpr (Q < 5) {
        constexpr int m = 1 << (4 - Q);   // lane xor mask
#pragma unroll
        for (int r = 0; r < 8; ++r) {
            float pr = __shfl_xor_sync(FULLMASK, re[r], m);
            float pi = __shfl_xor_sync(FULLMASK, im[r], m);
            float nr = fmaf(s, pi, c * re[r]);
            float ni = fmaf(-s, pr, c * im[r]);
            re[r] = nr;
            im[r] = ni;
        }
    } else {
        constexpr int m = 1 << (7 - Q);   // register bit mask (4,2,1)
#pragma unroll
        for (int r0 = 0; r0 < 8; ++r0) {
            if ((r0 & m) == 0) {
                const int r1 = r0 | m;
                const float a0r = re[r0], a0i = im[r0];
                const float a1r = re[r1], a1i = im[r1];
                re[r0] = fmaf(s, a1i, c * a0r);
                im[r0] = fmaf(-s, a1r, c * a0i);
                re[r1] = fmaf(s, a0i, c * a1r);
                im[r1] = fmaf(-s, a0r, c * a1i);
            }
        }
    }
}

template <int CM, int TM>
__device__ __forceinline__ void cnot_lane_lane(float (&re)[8], float (&im)[8], int lane) {
    const bool c = (lane & CM) != 0;
#pragma unroll
    for (int r = 0; r < 8; ++r) {
        float tr = __shfl_xor_sync(FULLMASK, re[r], TM);
        float ti = __shfl_xor_sync(FULLMASK, im[r], TM);
        re[r] = c ? tr : re[r];
        im[r] = c ? ti : im[r];
    }
}

__device__ __forceinline__ void cond_swap(float& a, float& b, bool c) {
    const float t0 = a, t1 = b;
    a = c ? t1 : t0;
    b = c ? t0 : t1;
}

__device__ __forceinline__ void swapf(float& a, float& b) {
    const float t = a; a = b; b = t;
}

__device__ __forceinline__ void cnot_ring(float (&re)[8], float (&im)[8], int lane) {
    // CNOT(q, (q+1)%8) for q = 0..7, in order.
    cnot_lane_lane<16, 8>(re, im, lane);  // q0 ctrl -> q1
    cnot_lane_lane<8, 4>(re, im, lane);   // q1 -> q2
    cnot_lane_lane<4, 2>(re, im, lane);   // q2 -> q3
    cnot_lane_lane<2, 1>(re, im, lane);   // q3 -> q4
    // q4 (lane bit0) ctrl -> q5 (reg bit2)
    {
        const bool c = (lane & 1) != 0;
#pragma unroll
        for (int r = 0; r < 4; ++r) {
            cond_swap(re[r], re[r + 4], c);
            cond_swap(im[r], im[r + 4], c);
        }
    }
    // q5 (reg bit2) ctrl -> q6 (reg bit1): swap (4,6),(5,7)  -- free permutation
    swapf(re[4], re[6]); swapf(im[4], im[6]);
    swapf(re[5], re[7]); swapf(im[5], im[7]);
    // q6 (reg bit1) ctrl -> q7 (reg bit0): swap (2,3),(6,7)
    swapf(re[2], re[3]); swapf(im[2], im[3]);
    swapf(re[6], re[7]); swapf(im[6], im[7]);
    // q7 (reg bit0) ctrl -> q0 (lane bit4): swap odd slots across lane^16
#pragma unroll
    for (int r = 1; r < 8; r += 2) {
        re[r] = __shfl_xor_sync(FULLMASK, re[r], 16);
        im[r] = __shfl_xor_sync(FULLMASK, im[r], 16);
    }
}

__global__ void __launch_bounds__(kThreads)
qconv_kernel(const float* __restrict__ x, const float* __restrict__ w,
             float* __restrict__ out) {
    __shared__ float s_cw[kOutCh * kNL * 8];
    __shared__ float s_sw[kOutCh * kNL * 8];
    const int tid = threadIdx.x;
    if (tid < kOutCh * kNL * 8) {
        float sv, cv;
        sincosf(0.5f * w[tid], &sv, &cv);
        s_cw[tid] = cv;
        s_sw[tid] = sv;
    }
    __syncthreads();

    const int warp = blockIdx.x * kWarpsPerBlock + (tid >> 5);
    const int lane = tid & 31;

    const int b = warp >> 12;        // / (64*64)
    const int ij = warp & 4095;
    const int i = ij >> 6;
    const int j = ij & 63;

    // Lane q<8 holds (cos, sin) of half the q-th patch angle; broadcast on use.
    float myc = 1.0f, mys = 0.0f;
    if (lane < 8) {
        const int c = lane >> 2;           // angle index = c*4 + di*2 + dj
        const int di = (lane >> 1) & 1;
        const int dj = lane & 1;
        const float ang =
            x[(((b * kInCh + c) * kH) + (2 * i + di)) * kW + (2 * j + dj)];
        sincosf(0.5f * ang, &mys, &myc);
    }

    // Embedded state (depends only on the patch -> shared across channels).
    float er[8], ei[8];
#pragma unroll
    for (int r = 0; r < 8; ++r) { er[r] = 0.0f; ei[r] = 0.0f; }
    if (lane == 0) er[0] = 1.0f;

#define EMB(Q) rx_gate<Q>(er, ei, __shfl_sync(FULLMASK, myc, Q), \
                                 __shfl_sync(FULLMASK, mys, Q))
    EMB(0); EMB(1); EMB(2); EMB(3); EMB(4); EMB(5); EMB(6); EMB(7);
#undef EMB

#pragma unroll 1
    for (int oc = 0; oc < kOutCh; ++oc) {
        float re[8], im[8];
#pragma unroll
        for (int r = 0; r < 8; ++r) { re[r] = er[r]; im[r] = ei[r]; }

#pragma unroll 1
        for (int l = 0; l < kNL; ++l) {
            const float* cc = &s_cw[(oc * kNL + l) * 8];
            const float* ss = &s_sw[(oc * kNL + l) * 8];
            rx_gate<0>(re, im, cc[0], ss[0]);
            rx_gate<1>(re, im, cc[1], ss[1]);
            rx_gate<2>(re, im, cc[2], ss[2]);
            rx_gate<3>(re, im, cc[3], ss[3]);
            rx_gate<4>(re, im, cc[4], ss[4]);
            rx_gate<5>(re, im, cc[5], ss[5]);
            rx_gate<6>(re, im, cc[6], ss[6]);
            rx_gate<7>(re, im, cc[7], ss[7]);
            cnot_ring(re, im, lane);
        }

        // <Z> on qubit 7 (register bit 0): even slots minus odd slots.
        float e = 0.0f;
#pragma unroll
        for (int r = 0; r < 8; ++r) {
            const float p = fmaf(re[r], re[r], im[r] * im[r]);
            e += (r & 1) ? -p : p;
        }
#pragma unroll
        for (int off = 16; off > 0; off >>= 1)
            e += __shfl_xor_sync(FULLMASK, e, off);
        if (lane == 0)
            out[((b * kOutCh + oc) * kHH + i) * kWW + j] = e;
    }
}

}  // namespace

extern "C" void kernel_launch(void* const* d_in, const int* /*in_sizes*/, int /*n_in*/,
                              void* d_out, int /*out_size*/) {
    const float* x = (const float*)d_in[0];
    const float* w = (const float*)d_in[1];
    float* out = (float*)d_out;
    qconv_kernel<<<kBlocks, kThreads>>>(x, w, out);
}

// round 2
// speedup vs baseline: 1.3502x; 1.3502x over previous
#include <cuda_runtime.h>

#define FULLMASK 0xffffffffu

namespace {

constexpr int kB = 2;
constexpr int kInCh = 2;
constexpr int kOutCh = 4;
constexpr int kH = 128;
constexpr int kW = 128;
constexpr int kHH = 64;
constexpr int kWW = 64;
constexpr int kNL = 4;
constexpr int kNPatch = kB * kHH * kWW;           // 8192 patches, one warp each
constexpr int kThreads = 256;
constexpr int kWarpsPerBlock = kThreads / 32;     // 8
constexpr int kBlocks = kNPatch / kWarpsPerBlock; // 1024

// ---------------------------------------------------------------------------
// GF(2) linear algebra for the CNOT ring (constexpr, correct by construction).
//
// CNOT ring (q -> q+1 mod 8, in order q=0..7) maps basis |v> -> |L v| with:
//   b1' = b1^b0; b2' = b2^b1'; ...; b7' = b7^b6'; b0' = b0^b7'
// i.e. forward:  b0' = b1^..^b7,  bk' = b0^..^bk (k>=1)
// inverse:       b0 = b0'^b7'; b1 = b0'^b1'^b7'; bk = b_{k-1}'^bk' (k>=2)
//
// Since RX is symmetric, RX on logical qubit q after k deferred rings acts on
// stored-index pairs differing by mask L^{-k} e_q. Measurement of logical
// bit 7 after 4 rings = parity(v & R) with R_j = bit7(L^4 e_j).
// ---------------------------------------------------------------------------

__host__ __device__ constexpr unsigned PAR(unsigned x) {
    x ^= x >> 4; x ^= x >> 2; x ^= x >> 1; return x & 1u;
}

__host__ __device__ constexpr unsigned LFWD(unsigned u) {
    unsigned r = PAR(u & 0xFEu);                 // bit0' = b1^..^b7
    for (int k = 1; k < 8; ++k)
        r |= PAR(u & ((2u << k) - 1u)) << k;     // bitk' = b0^..^bk
    return r;
}

__host__ __device__ constexpr unsigned LINV(unsigned u) {
    unsigned b0 = (u >> 0) & 1u, b1 = (u >> 1) & 1u, b2 = (u >> 2) & 1u,
             b3 = (u >> 3) & 1u, b4 = (u >> 4) & 1u, b5 = (u >> 5) & 1u,
             b6 = (u >> 6) & 1u, b7 = (u >> 7) & 1u;
    unsigned r = (b0 ^ b7);
    r |= (b0 ^ b1 ^ b7) << 1;
    r |= (b1 ^ b2) << 2;
    r |= (b2 ^ b3) << 3;
    r |= (b3 ^ b4) << 4;
    r |= (b4 ^ b5) << 5;
    r |= (b5 ^ b6) << 6;
    r |= (b6 ^ b7) << 7;
    return r;
}

// Mask (in qubit space) for RX on logical qubit q with k deferred rings.
__host__ __device__ constexpr unsigned MK(int k, int q) {
    unsigned m = 1u << q;
    for (int i = 0; i < k; ++i) m = LINV(m);
    return m;
}

// Measurement mask: bit j set iff bit7(L^4 e_j).
__host__ __device__ constexpr unsigned MEAS() {
    unsigned r = 0;
    for (int j = 0; j < 8; ++j) {
        unsigned v = 1u << j;
        for (int t = 0; t < 4; ++t) v = LFWD(v);
        if ((v >> 7) & 1u) r |= 1u << j;
    }
    return r;
}

// Physical layout: stored flat index bit (7-q) = qubit q.
// Lane id = flat bits [7:3]  => qubits 0..4 -> lane bits 4..0.
// Reg slot = flat bits [2:0] => qubits 5..7 -> reg bits 2..0.
__host__ __device__ constexpr unsigned laneMask(unsigned m) {
    unsigned r = 0;
    for (int q = 0; q <= 4; ++q) if ((m >> q) & 1u) r |= 1u << (4 - q);
    return r;
}
__host__ __device__ constexpr unsigned regMask(unsigned m) {
    unsigned r = 0;
    for (int q = 5; q <= 7; ++q) if ((m >> q) & 1u) r |= 1u << (7 - q);
    return r;
}
__host__ __device__ constexpr unsigned MSBIT(unsigned m) {
    unsigned b = 0;
    for (int i = 0; i < 8; ++i) if ((m >> i) & 1u) b = 1u << i;
    return b;
}

// RX between stored-index pairs differing by (lane mask LM, reg mask RM).
template <unsigned LM, unsigned RM>
__device__ __forceinline__ void rx_mask(float (&re)[8], float (&im)[8],
                                        float c, float s) {
    if constexpr (LM != 0) {
        float pr[8], pi[8];
#pragma unroll
        for (int r = 0; r < 8; ++r) {
            pr[r] = __shfl_xor_sync(FULLMASK, re[r ^ RM], LM);
            pi[r] = __shfl_xor_sync(FULLMASK, im[r ^ RM], LM);
        }
#pragma unroll
        for (int r = 0; r < 8; ++r) {
            re[r] = fmaf(s, pi[r], c * re[r]);
            im[r] = fmaf(-s, pr[r], c * im[r]);
        }
    } else {
        constexpr unsigned MB = MSBIT(RM);
#pragma unroll
        for (int r0 = 0; r0 < 8; ++r0) {
            if ((r0 & MB) == 0) {
                const int r1 = r0 ^ RM;
                const float a0r = re[r0], a0i = im[r0];
                const float a1r = re[r1], a1i = im[r1];
                re[r0] = fmaf(s, a1i, c * a0r);
                im[r0] = fmaf(-s, a1r, c * a0i);
                re[r1] = fmaf(s, a0i, c * a1r);
                im[r1] = fmaf(-s, a0r, c * a1i);
            }
        }
    }
}

#define GATE(K, Q) \
    rx_mask<laneMask(MK(K, Q)), regMask(MK(K, Q))>(re, im, cc[Q], ss[Q])
#define RXLAYER(K)                                         \
    do {                                                   \
        GATE(K, 0); GATE(K, 1); GATE(K, 2); GATE(K, 3);    \
        GATE(K, 4); GATE(K, 5); GATE(K, 6); GATE(K, 7);    \
    } while (0)

__global__ void __launch_bounds__(kThreads)
qconv_kernel(const float* __restrict__ x, const float* __restrict__ w,
             float* __restrict__ out) {
    __shared__ float s_cw[kOutCh * kNL * 8];
    __shared__ float s_sw[kOutCh * kNL * 8];
    const int tid = threadIdx.x;
    if (tid < kOutCh * kNL * 8) {
        float sv, cv;
        sincosf(0.5f * w[tid], &sv, &cv);
        s_cw[tid] = cv;
        s_sw[tid] = sv;
    }
    __syncthreads();

    const int warp = blockIdx.x * kWarpsPerBlock + (tid >> 5);
    const int lane = tid & 31;

    const int b = warp >> 12;
    const int ij = warp & 4095;
    const int i = ij >> 6;
    const int j = ij & 63;

    // Lane q<8 holds (cos, sin) of half the q-th patch angle.
    float myc = 1.0f, mys = 0.0f;
    if (lane < 8) {
        const int c = lane >> 2;
        const int di = (lane >> 1) & 1;
        const int dj = lane & 1;
        const float ang =
            x[(((b * kInCh + c) * kH) + (2 * i + di)) * kW + (2 * j + dj)];
        sincosf(0.5f * ang, &mys, &myc);
    }

    // Embedded state (shared across the 4 output channels). Embed uses k=0
    // masks (no rings pending yet).
    float er[8], ei[8];
#pragma unroll
    for (int r = 0; r < 8; ++r) { er[r] = 0.0f; ei[r] = 0.0f; }
    if (lane == 0) er[0] = 1.0f;

    {
        float (&re)[8] = er;
        float (&im)[8] = ei;
#define EGATE(Q) rx_mask<laneMask(MK(0, Q)), regMask(MK(0, Q))>( \
        re, im, __shfl_sync(FULLMASK, myc, Q), __shfl_sync(FULLMASK, mys, Q))
        EGATE(0); EGATE(1); EGATE(2); EGATE(3);
        EGATE(4); EGATE(5); EGATE(6); EGATE(7);
#undef EGATE
    }

    // Measurement sign masks (per-lane and per-register parts).
    constexpr unsigned ML = laneMask(MEAS());
    constexpr unsigned MR = regMask(MEAS());

#pragma unroll 1
    for (int oc = 0; oc < kOutCh; ++oc) {
        float re[8], im[8];
#pragma unroll
        for (int r = 0; r < 8; ++r) { re[r] = er[r]; im[r] = ei[r]; }

        // 4 layers; CNOT rings fully deferred into the layer-k RX masks.
        {
            const float* cc = &s_cw[(oc * kNL + 0) * 8];
            const float* ss = &s_sw[(oc * kNL + 0) * 8];
            RXLAYER(0);
        }
        {
            const float* cc = &s_cw[(oc * kNL + 1) * 8];
            const float* ss = &s_sw[(oc * kNL + 1) * 8];
            RXLAYER(1);
        }
        {
            const float* cc = &s_cw[(oc * kNL + 2) * 8];
            const float* ss = &s_sw[(oc * kNL + 2) * 8];
            RXLAYER(2);
        }
        {
            const float* cc = &s_cw[(oc * kNL + 3) * 8];
            const float* ss = &s_sw[(oc * kNL + 3) * 8];
            RXLAYER(3);
        }

        // <Z> on logical qubit 7 = sum_v (-1)^parity(v & MEAS) |amp_v|^2.
        float e = 0.0f;
#pragma unroll
        for (int r = 0; r < 8; ++r) {
            const float p = fmaf(re[r], re[r], im[r] * im[r]);
            e += (PAR(((unsigned)r) & MR) ? -p : p);
        }
        if (__popc(lane & (int)ML) & 1) e = -e;
#pragma unroll
        for (int off = 16; off > 0; off >>= 1)
            e += __shfl_xor_sync(FULLMASK, e, off);
        if (lane == 0)
            out[((b * kOutCh + oc) * kHH + i) * kWW + j] = e;
    }
}

}  // namespace

extern "C" void kernel_launch(void* const* d_in, const int* /*in_sizes*/, int /*n_in*/,
                              void* d_out, int /*out_size*/) {
    const float* x = (const float*)d_in[0];
    const float* w = (const float*)d_in[1];
    float* out = (float*)d_out;
    qconv_kernel<<<kBlocks, kThreads>>>(x, w, out);
}

// round 4
// speedup vs baseline: 6.4737x; 4.7945x over previous
#include <cuda_runtime.h>
#include <cstdint>

namespace {

constexpr unsigned FULL = 0xffffffffu;

// ---------------------------------------------------------------------------
// GF(2) 8x8 matrix algebra (constexpr).
// Circuit in X basis: RX -> RZ (diagonal), CNOT(q, q+1) -> CNOT(q+1, q),
// so each layer's ring becomes the linear basis map P:
//   v0'=v0^v1; v1'=v1^v2; ... v6'=v6^v7; v7'=v7^v0'  (sequential, q=0..7)
// Final state phase: Phi(v) = sum_g (theta_g/2) * (-1)^{(P^{-k_g} v)_{q_g}},
// k_g = #rings after gate g.  <Z7> = <phi|X7|phi>
//   = (1/256) sum_v cos( sum_{g: bit7(row_q(P^-k))=1} theta_g (-1)^{par(a_g&v)} )
// with a_g = row_q(P^{-k_g}).
// ---------------------------------------------------------------------------

struct M8 { uint8_t r[8]; };

__host__ __device__ constexpr M8 makeP() {
    M8 P{};
    for (int q = 0; q < 7; ++q) P.r[q] = uint8_t((1u << q) | (1u << (q + 1)));
    P.r[7] = uint8_t((1u << 7) | 3u);   // v7' = v7 ^ v0 ^ v1
    return P;
}
__host__ __device__ constexpr M8 ident() {
    M8 I{};
    for (int q = 0; q < 8; ++q) I.r[q] = uint8_t(1u << q);
    return I;
}
__host__ __device__ constexpr M8 matmul(const M8& A, const M8& B) {
    M8 C{};
    for (int q = 0; q < 8; ++q) {
        uint8_t row = 0;
        for (int k = 0; k < 8; ++k)
            if ((A.r[q] >> k) & 1u) row ^= B.r[k];
        C.r[q] = row;
    }
    return C;
}
__host__ __device__ constexpr M8 inverse(const M8& A) {  // Gauss-Jordan [A|I]
    unsigned m[8] = {};
    for (int q = 0; q < 8; ++q) m[q] = (unsigned)A.r[q] | (1u << (8 + q));
    for (int col = 0; col < 8; ++col) {
        int piv = col;
        while (!((m[piv] >> col) & 1u)) ++piv;
        unsigned t = m[col]; m[col] = m[piv]; m[piv] = t;
        for (int r = 0; r < 8; ++r)
            if (r != col && ((m[r] >> col) & 1u)) m[r] ^= m[col];
    }
    M8 R{};
    for (int q = 0; q < 8; ++q) R.r[q] = uint8_t(m[q] >> 8);
    return R;
}
__host__ __device__ constexpr M8 Pinv_pow(int k) {       // P^{-k}
    M8 Pi = inverse(makeP());
    M8 R = ident();
    for (int i = 0; i < k; ++i) R = matmul(Pi, R);
    return R;
}

// Weight gates: layer l (0..3) has k = 4-l rings after it. theta = w[c][l][q].
struct WGates { int n; uint8_t a[32]; uint8_t idx[32]; };
__host__ __device__ constexpr WGates makeWG() {
    WGates G{};
    for (int l = 0; l < 4; ++l) {
        M8 A = Pinv_pow(4 - l);
        for (int q = 0; q < 8; ++q)
            if ((A.r[q] >> 7) & 1u) {          // bit7 of row q <=> (A e7)_q
                G.a[G.n] = A.r[q];
                G.idx[G.n] = uint8_t(l * 8 + q);
                ++G.n;
            }
    }
    return G;
}
// Embed gates: k = 4 rings after. theta = x_q (patch angle q).
struct XGates { int n; uint8_t a[8]; uint8_t q[8]; };
__host__ __device__ constexpr XGates makeXG() {
    XGates G{};
    M8 A = Pinv_pow(4);
    for (int q = 0; q < 8; ++q)
        if ((A.r[q] >> 7) & 1u) {
            G.a[G.n] = A.r[q];
            G.q[G.n] = uint8_t(q);
            ++G.n;
        }
    return G;
}

// Per-channel tables: (cos, sin) of S_w(v), scaled by 1/256.
__device__ float2 g_tab[4 * 256];

__global__ void build_tab(const float* __restrict__ w) {
    constexpr WGates WG = makeWG();   // function-local constexpr: legal in
    const int c = blockIdx.x;         // device code without relaxed-constexpr
    const int v = threadIdx.x;        // 4 blocks x 256 threads
    float S = 0.f;
#pragma unroll
    for (int g = 0; g < WG.n; ++g) {
        const float th = __ldg(&w[c * 32 + (int)WG.idx[g]]);
        S += (__popc((int)WG.a[g] & v) & 1) ? -th : th;
    }
    float sv, cv;
    sincosf(S, &sv, &cv);             // accurate path; |S| can be ~200
    g_tab[c * 256 + v] = make_float2(cv * (1.f / 256.f), sv * (1.f / 256.f));
}

constexpr int kThreads = 128;                 // 4 warps / block
constexpr int kPatchesPerWarp = 4;
constexpr int kBlocks = 512;                  // 512*4*4 = 8192 patches

__global__ __launch_bounds__(kThreads)
void qconv_main(const float* __restrict__ x, float* __restrict__ out) {
    constexpr XGates XG = makeXG();
    const int tid = threadIdx.x;
    const int lane = tid & 31;
    const int wid = tid >> 5;
    const int wg = blockIdx.x * (kThreads / 32) + wid;

#pragma unroll 1
    for (int pi = 0; pi < kPatchesPerWarp; ++pi) {
        const int patch = wg * kPatchesPerWarp + pi;
        const int b = patch >> 12;
        const int ij = patch & 4095;
        const int i = ij >> 6;
        const int j = ij & 63;

        // Lane q<8 loads patch angle q (angle index = c*4 + di*2 + dj).
        float myx = 0.f;
        if (lane < 8) {
            const int c = lane >> 2, di = (lane >> 1) & 1, dj = lane & 1;
            myx = x[((b * 2 + c) * 128 + (2 * i + di)) * 128 + (2 * j + dj)];
        }

        // v = t*32 + lane (bits 0-4 = lane, bits 5-7 = t).
        // Per gate: sign(v) = par(a&lane) ^ par((a>>5)&t); lane part baked in y.
        float y[8];
#pragma unroll
        for (int g = 0; g < XG.n; ++g) {
            const float xv = __shfl_sync(FULL, myx, (int)XG.q[g]);
            y[g] = (__popc((int)XG.a[g] & lane) & 1) ? -xv : xv;
        }

        float a0 = 0.f, a1 = 0.f, a2 = 0.f, a3 = 0.f;
#pragma unroll
        for (int t = 0; t < 8; ++t) {
            float S = 0.f;
#pragma unroll
            for (int g = 0; g < XG.n; ++g)   // t-part signs fold to immediates
                S += (__popc(((int)XG.a[g] >> 5) & t) & 1) ? -y[g] : y[g];

            // Cody-Waite reduction to [-pi, pi], then fast HW sincos.
            const float k = rintf(S * 0.15915494309189535f);
            float r = fmaf(k, -6.283185482025146484f, S);
            r = fmaf(k, 1.7484556000744885e-7f, r);
            float sv, cv;
            __sincosf(r, &sv, &cv);

            const int v = t * 32 + lane;
            const float2 t0 = __ldg(&g_tab[v]);
            const float2 t1 = __ldg(&g_tab[256 + v]);
            const float2 t2 = __ldg(&g_tab[512 + v]);
            const float2 t3 = __ldg(&g_tab[768 + v]);
            // cos(Sw + Sx) = cw*cx - sw*sx
            a0 = fmaf(cv, t0.x, fmaf(-sv, t0.y, a0));
            a1 = fmaf(cv, t1.x, fmaf(-sv, t1.y, a1));
            a2 = fmaf(cv, t2.x, fmaf(-sv, t2.y, a2));
            a3 = fmaf(cv, t3.x, fmaf(-sv, t3.y, a3));
        }

#pragma unroll
        for (int o = 16; o > 0; o >>= 1) {
            a0 += __shfl_xor_sync(FULL, a0, o);
            a1 += __shfl_xor_sync(FULL, a1, o);
            a2 += __shfl_xor_sync(FULL, a2, o);
            a3 += __shfl_xor_sync(FULL, a3, o);
        }
        if (lane == 0) {
            const int base = ((b * 4) * 64 + i) * 64 + j;
            out[base] = a0;
            out[base + 4096] = a1;
            out[base + 2 * 4096] = a2;
            out[base + 3 * 4096] = a3;
        }
    }
}

}  // namespace

extern "C" void kernel_launch(void* const* d_in, const int* /*in_sizes*/, int /*n_in*/,
                              void* d_out, int /*out_size*/) {
    const float* x = (const float*)d_in[0];
    const float* w = (const float*)d_in[1];
    float* out = (float*)d_out;
    build_tab<<<4, 256>>>(w);
    qconv_main<<<kBlocks, kThreads>>>(x, out);
}

// round 5
// speedup vs baseline: 12.4183x; 1.9183x over previous
#include <cuda_runtime.h>
#include <cstdint>

namespace {

constexpr unsigned FULL = 0xffffffffu;

// ---------------------------------------------------------------------------
// GF(2) 8x8 matrix algebra (constexpr) — validated by the round-4 kernel.
// X basis: RX -> RZ (diagonal), each CNOT ring -> linear basis map P.
// <Z7> = (1/256) sum_v cos( sum_{active gates g} theta_g * (-1)^{par(a_g & v)} ),
// gate active iff bit7 of row q of P^{-k} is set, a_g = that row, k = rings
// remaining after the gate.
// Key collapse: embed gates (k=4) active only for q=0 and q=4
// (P^{-4} e7 = 0x11), so the data-dependent phase is +-x0 +- x4: 4 patterns.
// ---------------------------------------------------------------------------

struct M8 { uint8_t r[8]; };

__host__ __device__ constexpr M8 makeP() {
    M8 P{};
    for (int q = 0; q < 7; ++q) P.r[q] = uint8_t((1u << q) | (1u << (q + 1)));
    P.r[7] = uint8_t((1u << 7) | 3u);
    return P;
}
__host__ __device__ constexpr M8 ident() {
    M8 I{};
    for (int q = 0; q < 8; ++q) I.r[q] = uint8_t(1u << q);
    return I;
}
__host__ __device__ constexpr M8 matmul(const M8& A, const M8& B) {
    M8 C{};
    for (int q = 0; q < 8; ++q) {
        uint8_t row = 0;
        for (int k = 0; k < 8; ++k)
            if ((A.r[q] >> k) & 1u) row ^= B.r[k];
        C.r[q] = row;
    }
    return C;
}
__host__ __device__ constexpr M8 inverse(const M8& A) {
    unsigned m[8] = {};
    for (int q = 0; q < 8; ++q) m[q] = (unsigned)A.r[q] | (1u << (8 + q));
    for (int col = 0; col < 8; ++col) {
        int piv = col;
        while (!((m[piv] >> col) & 1u)) ++piv;
        unsigned t = m[col]; m[col] = m[piv]; m[piv] = t;
        for (int r = 0; r < 8; ++r)
            if (r != col && ((m[r] >> col) & 1u)) m[r] ^= m[col];
    }
    M8 R{};
    for (int q = 0; q < 8; ++q) R.r[q] = uint8_t(m[q] >> 8);
    return R;
}
__host__ __device__ constexpr M8 Pinv_pow(int k) {
    M8 Pi = inverse(makeP());
    M8 R = ident();
    for (int i = 0; i < k; ++i) R = matmul(Pi, R);
    return R;
}

struct WGates { int n; uint8_t a[32]; uint8_t idx[32]; };
__host__ __device__ constexpr WGates makeWG() {
    WGates G{};
    for (int l = 0; l < 4; ++l) {
        M8 A = Pinv_pow(4 - l);
        for (int q = 0; q < 8; ++q)
            if ((A.r[q] >> 7) & 1u) {
                G.a[G.n] = A.r[q];
                G.idx[G.n] = uint8_t(l * 8 + q);
                ++G.n;
            }
    }
    return G;
}
struct XGates { int n; uint8_t a[8]; uint8_t q[8]; };
__host__ __device__ constexpr XGates makeXG() {
    XGates G{};
    M8 A = Pinv_pow(4);
    for (int q = 0; q < 8; ++q)
        if ((A.r[q] >> 7) & 1u) {
            G.a[G.n] = A.r[q];
            G.q[G.n] = uint8_t(q);
            ++G.n;
        }
    return G;
}

constexpr int kThreads = 256;
constexpr int kBlocks = 32;   // 32 * 256 = 8192 output pixels, 1 per thread

__global__ __launch_bounds__(kThreads)
void qconv_fused(const float* __restrict__ x, const float* __restrict__ w,
                 float* __restrict__ out) {
    constexpr WGates WG = makeWG();
    constexpr XGates XG = makeXG();
    static_assert(XG.n == 2, "embed collapse assumption violated");
    constexpr int MA = XG.a[0];   // sign mask of gate on qubit XG.q[0]
    constexpr int MB = XG.a[1];   // sign mask of gate on qubit XG.q[1]

    __shared__ float s_w[128];
    __shared__ float s_part[8][4];
    __shared__ float s_tab[4][4];   // per channel: A, B, D, E (scaled 1/256)

    const int tid = threadIdx.x;
    const int lane = tid & 31;
    const int wid = tid >> 5;

    if (tid < 128) s_w[tid] = w[tid];
    __syncthreads();

    // ---- Phase 1: weight-only coset sums (redundant per block, tiny). ----
    // Threads [c*64, c*64+64) handle channel c; each covers 4 of the 256 v.
    const int c = tid >> 6;
    const int vt = tid & 63;
    float A = 0.f, B = 0.f, D = 0.f, E = 0.f;
#pragma unroll
    for (int k = 0; k < 4; ++k) {
        const int v = vt | (k << 6);
        float S = 0.f;
#pragma unroll
        for (int g = 0; g < WG.n; ++g) {
            const float th = s_w[c * 32 + (int)WG.idx[g]];
            S += (__popc((int)WG.a[g] & v) & 1) ? -th : th;
        }
        float sv, cv;
        sincosf(S, &sv, &cv);
        const int pA = __popc(MA & v) & 1;
        const int pB = __popc(MB & v) & 1;
        const float sg = pA ? -sv : sv;     // sin sign = (1 - 2*pA), both groups
        if (pA == pB) { A += cv; B += sg; }
        else          { D += cv; E += sg; }
    }
    // Deterministic reduction: intra-warp shfl, then fixed-order combine.
#pragma unroll
    for (int off = 16; off > 0; off >>= 1) {
        A += __shfl_xor_sync(FULL, A, off);
        B += __shfl_xor_sync(FULL, B, off);
        D += __shfl_xor_sync(FULL, D, off);
        E += __shfl_xor_sync(FULL, E, off);
    }
    if (lane == 0) {
        s_part[wid][0] = A; s_part[wid][1] = B;
        s_part[wid][2] = D; s_part[wid][3] = E;
    }
    __syncthreads();
    if (tid < 16) {
        const int cc = tid >> 2, comp = tid & 3;
        s_tab[cc][comp] =
            (s_part[2 * cc][comp] + s_part[2 * cc + 1][comp]) * (1.f / 256.f);
    }
    __syncthreads();

    // ---- Phase 2: one output pixel per thread. ----
    const int pixel = blockIdx.x * kThreads + tid;
    const int b = pixel >> 12;
    const int i = (pixel >> 6) & 63;
    const int j = pixel & 63;

    // Angle of embed gate on qubit q: patch angle index q = c*4 + di*2 + dj.
    constexpr int q0 = XG.q[0], q1 = XG.q[1];
    constexpr int c0 = q0 >> 2, d0i = (q0 >> 1) & 1, d0j = q0 & 1;
    constexpr int c1 = q1 >> 2, d1i = (q1 >> 1) & 1, d1j = q1 & 1;
    const float x0 = x[((b * 2 + c0) * 128 + (2 * i + d0i)) * 128 + (2 * j + d0j)];
    const float x1 = x[((b * 2 + c1) * 128 + (2 * i + d1i)) * 128 + (2 * j + d1j)];

    float sp, cp, sm, cm;
    sincosf(x0 + x1, &sp, &cp);
    sincosf(x0 - x1, &sm, &cm);

    const int base = ((b * 4) * 64 + i) * 64 + j;
#pragma unroll
    for (int oc = 0; oc < 4; ++oc) {
        const float r = fmaf(s_tab[oc][0], cp,
                        fmaf(-s_tab[oc][1], sp,
                        fmaf(s_tab[oc][2], cm, -s_tab[oc][3] * sm)));
        out[base + oc * 4096] = r;
    }
}

}  // namespace

extern "C" void kernel_launch(void* const* d_in, const int* /*in_sizes*/, int /*n_in*/,
                              void* d_out, int /*out_size*/) {
    const float* x = (const float*)d_in[0];
    const float* w = (const float*)d_in[1];
    float* out = (float*)d_out;
    qconv_fused<<<kBlocks, kThreads>>>(x, w, out);
}

// round 6
// speedup vs baseline: 12.6618x; 1.0196x over previous
#include <cuda_runtime.h>
#include <cstdint>

namespace {

constexpr unsigned FULL = 0xffffffffu;

// ---------------------------------------------------------------------------
// GF(2) 8x8 matrix algebra (constexpr) — validated by rounds 4 and 5.
// X basis: RX -> RZ (diagonal), each CNOT ring -> linear basis map P.
// <Z7> = (1/256) sum_v cos( sum_{active g} theta_g * (-1)^{par(a_g & v)} ),
// gate active iff bit7 of row q of P^{-k} set; a_g = that row; k = rings left.
// Embed gates collapse to qubits {0,4} (P^{-4} e7 = 0x11) => data phase is
// +-x0 +- x4 and the 256-term sum factors through 4 weight-only coset sums.
// ---------------------------------------------------------------------------

struct M8 { uint8_t r[8]; };

__host__ __device__ constexpr M8 makeP() {
    M8 P{};
    for (int q = 0; q < 7; ++q) P.r[q] = uint8_t((1u << q) | (1u << (q + 1)));
    P.r[7] = uint8_t((1u << 7) | 3u);
    return P;
}
__host__ __device__ constexpr M8 ident() {
    M8 I{};
    for (int q = 0; q < 8; ++q) I.r[q] = uint8_t(1u << q);
    return I;
}
__host__ __device__ constexpr M8 matmul(const M8& A, const M8& B) {
    M8 C{};
    for (int q = 0; q < 8; ++q) {
        uint8_t row = 0;
        for (int k = 0; k < 8; ++k)
            if ((A.r[q] >> k) & 1u) row ^= B.r[k];
        C.r[q] = row;
    }
    return C;
}
__host__ __device__ constexpr M8 inverse(const M8& A) {
    unsigned m[8] = {};
    for (int q = 0; q < 8; ++q) m[q] = (unsigned)A.r[q] | (1u << (8 + q));
    for (int col = 0; col < 8; ++col) {
        int piv = col;
        while (!((m[piv] >> col) & 1u)) ++piv;
        unsigned t = m[col]; m[col] = m[piv]; m[piv] = t;
        for (int r = 0; r < 8; ++r)
            if (r != col && ((m[r] >> col) & 1u)) m[r] ^= m[col];
    }
    M8 R{};
    for (int q = 0; q < 8; ++q) R.r[q] = uint8_t(m[q] >> 8);
    return R;
}
__host__ __device__ constexpr M8 Pinv_pow(int k) {
    M8 Pi = inverse(makeP());
    M8 R = ident();
    for (int i = 0; i < k; ++i) R = matmul(Pi, R);
    return R;
}

struct WGates { int n; uint8_t a[32]; uint8_t idx[32]; };
__host__ __device__ constexpr WGates makeWG() {
    WGates G{};
    for (int l = 0; l < 4; ++l) {
        M8 A = Pinv_pow(4 - l);
        for (int q = 0; q < 8; ++q)
            if ((A.r[q] >> 7) & 1u) {
                G.a[G.n] = A.r[q];
                G.idx[G.n] = uint8_t(l * 8 + q);
                ++G.n;
            }
    }
    return G;
}
struct XGates { int n; uint8_t a[8]; uint8_t q[8]; };
__host__ __device__ constexpr XGates makeXG() {
    XGates G{};
    M8 A = Pinv_pow(4);
    for (int q = 0; q < 8; ++q)
        if ((A.r[q] >> 7) & 1u) {
            G.a[G.n] = A.r[q];
            G.q[G.n] = uint8_t(q);
            ++G.n;
        }
    return G;
}

constexpr int kThreads = 256;
constexpr int kPixPerBlock = 64;
constexpr int kBlocks = 8192 / kPixPerBlock;   // 128 blocks -> 128 SMs busy

__device__ __forceinline__ void cw_sincos(float S, float& sv, float& cv) {
    // Cody-Waite to [-pi, pi] then MUFU sincos (validated path, round 4).
    const float k = rintf(S * 0.15915494309189535f);
    float r = fmaf(k, -6.283185482025146484f, S);
    r = fmaf(k, 1.7484556000744885e-7f, r);
    __sincosf(r, &sv, &cv);
}

__global__ __launch_bounds__(kThreads)
void qconv_fused(const float* __restrict__ x, const float* __restrict__ w,
                 float* __restrict__ out) {
    constexpr WGates WG = makeWG();
    constexpr XGates XG = makeXG();
    static_assert(XG.n == 2, "embed collapse assumption violated");
    constexpr int MA = XG.a[0];
    constexpr int MB = XG.a[1];

    __shared__ float s_w[128];
    __shared__ float s_part[8][4];
    __shared__ float s_tab[4][4];   // per channel: A, B, D, E (x 1/256)

    const int tid = threadIdx.x;
    const int lane = tid & 31;
    const int wid = tid >> 5;

    // ---- Prefetch pixel inputs early (hide DRAM latency under phase 1). ----
    float x0 = 0.f, x1 = 0.f;
    int base = 0;
    if (tid < kPixPerBlock) {
        const int pixel = blockIdx.x * kPixPerBlock + tid;
        const int b = pixel >> 12;
        const int i = (pixel >> 6) & 63;
        const int j = pixel & 63;
        constexpr int q0 = XG.q[0], q1 = XG.q[1];
        constexpr int c0 = q0 >> 2, d0i = (q0 >> 1) & 1, d0j = q0 & 1;
        constexpr int c1 = q1 >> 2, d1i = (q1 >> 1) & 1, d1j = q1 & 1;
        x0 = __ldg(&x[((b * 2 + c0) * 128 + (2 * i + d0i)) * 128 + (2 * j + d0j)]);
        x1 = __ldg(&x[((b * 2 + c1) * 128 + (2 * i + d1i)) * 128 + (2 * j + d1j)]);
        base = ((b * 4) * 64 + i) * 64 + j;
    }
    if (tid < 128) s_w[tid] = __ldg(&w[tid]);
    __syncthreads();

    // ---- Phase 1: weight coset sums. Thread covers channel c = tid>>6,
    // low-bits vt = tid&63, all 4 high-bit combos k via Walsh split. ----
    const int c = tid >> 6;
    const int vt = tid & 63;

    float T0 = 0.f, T1 = 0.f, T2 = 0.f, T3 = 0.f;
#pragma unroll
    for (int g = 0; g < WG.n; ++g) {
        const float th = s_w[c * 32 + (int)WG.idx[g]];
        const float sth = (__popc((int)WG.a[g] & 63 & vt) & 1) ? -th : th;
        const int grp = ((int)WG.a[g] >> 6) & 3;   // (bit6, bit7) of mask
        if (grp == 0) T0 += sth;
        else if (grp == 1) T1 += sth;
        else if (grp == 2) T2 += sth;
        else T3 += sth;
    }

    float A = 0.f, B = 0.f, D = 0.f, E = 0.f;
#pragma unroll
    for (int k = 0; k < 4; ++k) {
        const float f1 = (k & 1) ? -T1 : T1;
        const float f2 = (k & 2) ? -T2 : T2;
        const float f3 = (((k ^ (k >> 1)) & 1)) ? -T3 : T3;  // sign (-1)^(k0^k1)
        const float S = T0 + f1 + f2 + f3;
        float sv, cv;
        cw_sincos(S, sv, cv);
        const int v = vt | (k << 6);
        const int pA = __popc(MA & v) & 1;
        const int pB = __popc(MB & v) & 1;
        const float sg = pA ? -sv : sv;
        if (pA == pB) { A += cv; B += sg; }
        else          { D += cv; E += sg; }
    }

    // Deterministic fixed-order reductions.
#pragma unroll
    for (int off = 16; off > 0; off >>= 1) {
        A += __shfl_xor_sync(FULL, A, off);
        B += __shfl_xor_sync(FULL, B, off);
        D += __shfl_xor_sync(FULL, D, off);
        E += __shfl_xor_sync(FULL, E, off);
    }
    if (lane == 0) {
        s_part[wid][0] = A; s_part[wid][1] = B;
        s_part[wid][2] = D; s_part[wid][3] = E;
    }
    __syncthreads();
    if (tid < 16) {
        const int cc = tid >> 2, comp = tid & 3;
        s_tab[cc][comp] =
            (s_part[2 * cc][comp] + s_part[2 * cc + 1][comp]) * (1.f / 256.f);
    }
    __syncthreads();

    // ---- Phase 2: one output pixel per thread (tid < 64). ----
    if (tid < kPixPerBlock) {
        float sp, cp, sm, cm;
        cw_sincos(x0 + x1, sp, cp);
        cw_sincos(x0 - x1, sm, cm);
#pragma unroll
        for (int oc = 0; oc < 4; ++oc) {
            const float r = fmaf(s_tab[oc][0], cp,
                            fmaf(-s_tab[oc][1], sp,
                            fmaf(s_tab[oc][2], cm, -s_tab[oc][3] * sm)));
            out[base + oc * 4096] = r;
        }
    }
}

}  // namespace

extern "C" void kernel_launch(void* const* d_in, const int* /*in_sizes*/, int /*n_in*/,
                              void* d_out, int /*out_size*/) {
    const float* x = (const float*)d_in[0];
    const float* w = (const float*)d_in[1];
    float* out = (float*)d_out;
    qconv_fused<<<kBlocks, kThreads>>>(x, w, out);
}